// round 14
// baseline (speedup 1.0000x reference)
#include <cuda_runtime.h>
#include <cuda_fp16.h>
#include <math.h>
#include <stdint.h>

#define N_CTX   4096
#define D_MODEL 2048

// ---------------- scratch (allocation-free rule: device globals) ----------
__device__ float  g_S   [(size_t)N_CTX * N_CTX];       // scores (fp32)
__device__ __half g_Ehi [(size_t)N_CTX * D_MODEL];
__device__ __half g_Elo [(size_t)N_CTX * D_MODEL];
__device__ __half g_qkThi[(size_t)D_MODEL * D_MODEL];
__device__ __half g_qkTlo[(size_t)D_MODEL * D_MODEL];
__device__ __half g_ovThi[(size_t)D_MODEL * D_MODEL];
__device__ __half g_ovTlo[(size_t)D_MODEL * D_MODEL];
__device__ __half g_Qhi [(size_t)N_CTX * D_MODEL];
__device__ __half g_Qlo [(size_t)N_CTX * D_MODEL];
__device__ __half g_Vthi[(size_t)D_MODEL * N_CTX];
__device__ __half g_Vtlo[(size_t)D_MODEL * N_CTX];
__device__ __half g_Phi [(size_t)N_CTX * N_CTX];
__device__ __half g_Plo [(size_t)N_CTX * N_CTX];

// ---------------- helpers ---------------------------------------------------
__device__ __forceinline__ uint32_t smem_u32(const void* p) {
    uint32_t a;
    asm("{ .reg .u64 t; cvta.to.shared.u64 t, %1; cvt.u32.u64 %0, t; }"
        : "=r"(a) : "l"(p));
    return a;
}
#define SWZ(o) ((o) ^ (((o) >> 3) & 0x70))

__device__ __forceinline__ uint32_t f2h2(float x, float y) {
    __half2 h = __floats2half2_rn(x, y);
    return reinterpret_cast<uint32_t&>(h);
}
__device__ __forceinline__ void ldsm_x4(uint32_t* r, uint32_t addr) {
    asm volatile("ldmatrix.sync.aligned.m8n8.x4.shared.b16 {%0,%1,%2,%3}, [%4];"
                 : "=r"(r[0]), "=r"(r[1]), "=r"(r[2]), "=r"(r[3]) : "r"(addr));
}
__device__ __forceinline__ void mma16816(float* c, const uint32_t* a, const uint32_t* b) {
    asm volatile(
        "mma.sync.aligned.m16n8k16.row.col.f32.f16.f16.f32 "
        "{%0,%1,%2,%3}, {%4,%5,%6,%7}, {%8,%9}, {%0,%1,%2,%3};"
        : "+f"(c[0]), "+f"(c[1]), "+f"(c[2]), "+f"(c[3])
        : "r"(a[0]), "r"(a[1]), "r"(a[2]), "r"(a[3]), "r"(b[0]), "r"(b[1]));
}
#define CP_ASYNC16(smem, gptr) \
    asm volatile("cp.async.cg.shared.global [%0], [%1], 16;" \
                 :: "r"(smem), "l"(gptr) : "memory")
#define CP_COMMIT()  asm volatile("cp.async.commit_group;" ::: "memory")
#define CP_WAIT1()   asm volatile("cp.async.wait_group 1;" ::: "memory")

// Per-stage SMEM: four 128x64 f16 tiles (SW128 layout, 128B rows), 16 KB each.
static constexpr int OFF_AH = 0;
static constexpr int OFF_AL = 16384;
static constexpr int OFF_BH = 32768;
static constexpr int OFF_BL = 49152;
static constexpr int STAGE_BYTES = 65536;
static constexpr int STAGES = 3;
static constexpr int SMEM_BYTES = STAGES * STAGE_BYTES;   // 192 KB

// ---------------------------------------------------------------------------
// Pipelined split-fp16 HMMA GEMM:  C[M,N] = A[M,K] @ B[N,K]^T
//   512 threads: 4x4 warp grid, 32x32 warp tile (2 mt x 4 nt m16n8 tiles).
//   A,B given as (hi,lo) f16 pairs, K-major. 3 MMA terms: HH + HL + LH.
// ---------------------------------------------------------------------------
template<bool SKIP_UPPER, bool KLIMIT, bool MASK, bool F16OUT>
__global__ __launch_bounds__(512, 1)
void gemm_f16(const __half* __restrict__ Ahi, const __half* __restrict__ Alo,
              const __half* __restrict__ Bhi, const __half* __restrict__ Blo,
              float* __restrict__ C, __half* __restrict__ Chi, __half* __restrict__ Clo,
              int K, int lda, int ldb, int ldc)
{
    extern __shared__ char sm[];
    const int bx = blockIdx.x, by = blockIdx.y;
    if (SKIP_UPPER && bx > by) return;

    int Kend = K;
    if (KLIMIT) { int lim = (by + 1) * 128; Kend = lim < K ? lim : K; }
    const int nc = Kend >> 6;     // 64-wide K chunks (always >= 2 here)

    const uint32_t sb = smem_u32(sm);
    const int tid  = threadIdx.x;
    const int wid  = tid >> 5;
    const int lane = tid & 31;
    const int warpM = (wid & 3) * 32;    // 4 warps down M
    const int warpN = (wid >> 2) * 32;   // 4 warps across N

    float acc[2][4][4];
#pragma unroll
    for (int mt = 0; mt < 2; mt++)
#pragma unroll
        for (int nt = 0; nt < 4; nt++)
#pragma unroll
            for (int q = 0; q < 4; q++) acc[mt][nt][q] = 0.0f;

    const __half* AhB = Ahi + (size_t)by * 128 * lda;
    const __half* AlB = Alo + (size_t)by * 128 * lda;
    const __half* BhB = Bhi + (size_t)bx * 128 * ldb;
    const __half* BlB = Blo + (size_t)bx * 128 * ldb;

    auto issue = [&](int c) {
        if (c < nc) {
            const int k0 = c << 6;
            const uint32_t st = sb + (c % STAGES) * STAGE_BYTES;
#pragma unroll
            for (int q = 0; q < 2; q++) {
                int i = tid + (q << 9);          // 0..1023
                int r = i >> 3, c16 = i & 7;
                uint32_t so = SWZ((uint32_t)(r * 128 + c16 * 16));
                size_t goA = (size_t)r * lda + k0 + c16 * 8;
                size_t goB = (size_t)r * ldb + k0 + c16 * 8;
                CP_ASYNC16(st + OFF_AH + so, AhB + goA);
                CP_ASYNC16(st + OFF_AL + so, AlB + goA);
                CP_ASYNC16(st + OFF_BH + so, BhB + goB);
                CP_ASYNC16(st + OFF_BL + so, BlB + goB);
            }
        }
        CP_COMMIT();
    };

    // ldmatrix lane addressing (constant across chunks)
    const int a_row_l = lane & 15;
    const int a_kh_l  = ((lane >> 4) & 1) * 8;
    const int b_row_l = (lane & 7) + ((lane >> 4) & 1) * 8;
    const int b_kh_l  = ((lane >> 3) & 1) * 8;

    issue(0);
    issue(1);

    for (int c = 0; c < nc; c++) {
        CP_WAIT1();            // chunk c resident (only c+1 may still be in flight)
        __syncthreads();       // all warps done reading stage (c-1)%3; c's data visible

        issue(c + 2);          // refill the stage freed by chunk c-1

        const uint32_t st = sb + (c % STAGES) * STAGE_BYTES;
#pragma unroll
        for (int kk = 0; kk < 4; kk++) {
            uint32_t aH[2][4], aL[2][4], bH[2][4], bL[2][4];
#pragma unroll
            for (int mt = 0; mt < 2; mt++) {
                int row = warpM + mt * 16 + a_row_l;
                uint32_t off = SWZ((uint32_t)(row * 128 + (kk * 16 + a_kh_l) * 2));
                ldsm_x4(aH[mt], st + OFF_AH + off);
                ldsm_x4(aL[mt], st + OFF_AL + off);
            }
#pragma unroll
            for (int np = 0; np < 2; np++) {
                int row = warpN + np * 16 + b_row_l;
                uint32_t off = SWZ((uint32_t)(row * 128 + (kk * 16 + b_kh_l) * 2));
                ldsm_x4(bH[np], st + OFF_BH + off);
                ldsm_x4(bL[np], st + OFF_BL + off);
            }
#pragma unroll
            for (int mt = 0; mt < 2; mt++)
#pragma unroll
                for (int nt = 0; nt < 4; nt++)
                    mma16816(acc[mt][nt], aH[mt], &bH[nt >> 1][(nt & 1) * 2]);
#pragma unroll
            for (int mt = 0; mt < 2; mt++)
#pragma unroll
                for (int nt = 0; nt < 4; nt++)
                    mma16816(acc[mt][nt], aH[mt], &bL[nt >> 1][(nt & 1) * 2]);
#pragma unroll
            for (int mt = 0; mt < 2; mt++)
#pragma unroll
                for (int nt = 0; nt < 4; nt++)
                    mma16816(acc[mt][nt], aL[mt], &bH[nt >> 1][(nt & 1) * 2]);
        }
    }

    // ---- epilogue -----------------------------------------------------------
    const int g  = lane >> 2;
    const int t2 = (lane & 3) * 2;
#pragma unroll
    for (int mt = 0; mt < 2; mt++) {
        int grow0 = by * 128 + warpM + mt * 16 + g;
        int grow1 = grow0 + 8;
#pragma unroll
        for (int nt = 0; nt < 4; nt++) {
            int gcol = bx * 128 + warpN + nt * 8 + t2;
            float2 v0 = make_float2(acc[mt][nt][0], acc[mt][nt][1]);
            float2 v1 = make_float2(acc[mt][nt][2], acc[mt][nt][3]);
            if (F16OUT) {
                float hx0 = __half2float(__float2half_rn(v0.x));
                float hy0 = __half2float(__float2half_rn(v0.y));
                float hx1 = __half2float(__float2half_rn(v1.x));
                float hy1 = __half2float(__float2half_rn(v1.y));
                *(uint32_t*)(Chi + (size_t)grow0 * ldc + gcol) = f2h2(v0.x, v0.y);
                *(uint32_t*)(Clo + (size_t)grow0 * ldc + gcol) = f2h2(v0.x - hx0, v0.y - hy0);
                *(uint32_t*)(Chi + (size_t)grow1 * ldc + gcol) = f2h2(v1.x, v1.y);
                *(uint32_t*)(Clo + (size_t)grow1 * ldc + gcol) = f2h2(v1.x - hx1, v1.y - hy1);
            } else {
                if (MASK) {
                    if (gcol     > grow0) v0.x = -INFINITY;
                    if (gcol + 1 > grow0) v0.y = -INFINITY;
                    if (gcol     > grow1) v1.x = -INFINITY;
                    if (gcol + 1 > grow1) v1.y = -INFINITY;
                }
                *(float2*)(C + (size_t)grow0 * ldc + gcol) = v0;
                *(float2*)(C + (size_t)grow1 * ldc + gcol) = v1;
            }
        }
    }
}

// ---------------------------------------------------------------------------
// fp32 -> (hi, lo) f16 elementwise split (for E)
// ---------------------------------------------------------------------------
__global__ void convert_hilo(const float* __restrict__ in,
                             __half* __restrict__ hi, __half* __restrict__ lo, int n4)
{
    int idx = blockIdx.x * blockDim.x + threadIdx.x;
    if (idx >= n4) return;
    float4 v = ((const float4*)in)[idx];
    float hx = __half2float(__float2half_rn(v.x));
    float hy = __half2float(__float2half_rn(v.y));
    float hz = __half2float(__float2half_rn(v.z));
    float hw = __half2float(__float2half_rn(v.w));
    ((uint2*)hi)[idx] = make_uint2(f2h2(v.x, v.y), f2h2(v.z, v.w));
    ((uint2*)lo)[idx] = make_uint2(f2h2(v.x - hx, v.y - hy), f2h2(v.z - hz, v.w - hw));
}

// ---------------------------------------------------------------------------
// 2048x2048 fp32 transpose + split to (hi, lo) f16 (for qk, ov)
// ---------------------------------------------------------------------------
__global__ void transpose_hilo2048(const float* __restrict__ in,
                                   __half* __restrict__ ohi, __half* __restrict__ olo)
{
    __shared__ float t[32][33];
    int x = blockIdx.x * 32 + threadIdx.x;
    int y = blockIdx.y * 32 + threadIdx.y;
#pragma unroll
    for (int j = 0; j < 32; j += 8)
        t[threadIdx.y + j][threadIdx.x] = in[(size_t)(y + j) * D_MODEL + x];
    __syncthreads();
    x = blockIdx.y * 32 + threadIdx.x;
    y = blockIdx.x * 32 + threadIdx.y;
#pragma unroll
    for (int j = 0; j < 32; j += 8) {
        float v  = t[threadIdx.x][threadIdx.y + j];
        __half h = __float2half_rn(v);
        size_t o = (size_t)(y + j) * D_MODEL + x;
        ohi[o] = h;
        olo[o] = __float2half_rn(v - __half2float(h));
    }
}

// ---------------------------------------------------------------------------
// Row softmax (causal): reads fp32 S, writes (hi, lo) f16 P,
// zero-padded up to each row's 128-block limit.
// ---------------------------------------------------------------------------
__global__ void softmax_kernel(const float* __restrict__ S,
                               __half* __restrict__ Phi, __half* __restrict__ Plo)
{
    const int row   = blockIdx.x;
    const int n     = row + 1;
    const int limit = ((row >> 7) + 1) << 7;
    const float* s = S + (size_t)row * N_CTX;

    __shared__ float red[32];
    const int lane = threadIdx.x & 31;
    const int wid  = threadIdx.x >> 5;

    float m = -INFINITY;
    for (int j = threadIdx.x; j < n; j += 256) m = fmaxf(m, s[j]);
#pragma unroll
    for (int o = 16; o; o >>= 1) m = fmaxf(m, __shfl_xor_sync(0xffffffffu, m, o));
    if (lane == 0) red[wid] = m;
    __syncthreads();
    if (threadIdx.x < 32) {
        float v = (threadIdx.x < 8) ? red[threadIdx.x] : -INFINITY;
#pragma unroll
        for (int o = 4; o; o >>= 1) v = fmaxf(v, __shfl_xor_sync(0xffffffffu, v, o));
        if (threadIdx.x == 0) red[0] = v;
    }
    __syncthreads();
    m = red[0];
    __syncthreads();

    float sum = 0.0f;
    for (int j = threadIdx.x; j < n; j += 256) sum += __expf(s[j] - m);
#pragma unroll
    for (int o = 16; o; o >>= 1) sum += __shfl_xor_sync(0xffffffffu, sum, o);
    if (lane == 0) red[wid] = sum;
    __syncthreads();
    if (threadIdx.x < 32) {
        float v = (threadIdx.x < 8) ? red[threadIdx.x] : 0.0f;
#pragma unroll
        for (int o = 4; o; o >>= 1) v += __shfl_xor_sync(0xffffffffu, v, o);
        if (threadIdx.x == 0) red[0] = v;
    }
    __syncthreads();
    const float inv = 1.0f / red[0];

    __half* phi = Phi + (size_t)row * N_CTX;
    __half* plo = Plo + (size_t)row * N_CTX;
    for (int j = threadIdx.x; j < limit; j += 256) {
        float p = (j < n) ? __expf(s[j] - m) * inv : 0.0f;
        __half h = __float2half_rn(p);
        phi[j] = h;
        plo[j] = __float2half_rn(p - __half2float(h));
    }
}

// ---------------------------------------------------------------------------
extern "C" void kernel_launch(void* const* d_in, const int* in_sizes, int n_in,
                              void* d_out, int out_size)
{
    const float* E  = (const float*)d_in[0];   // [4096, 2048]
    const float* qk = (const float*)d_in[1];   // [2048, 2048]
    const float* ov = (const float*)d_in[2];   // [2048, 2048]
    float* out = (float*)d_out;                // [4096, 2048]

    float* S;
    __half *Ehi, *Elo, *qkThi, *qkTlo, *ovThi, *ovTlo;
    __half *Qhi, *Qlo, *Vthi, *Vtlo, *Phi, *Plo;
    cudaGetSymbolAddress((void**)&S,     g_S);
    cudaGetSymbolAddress((void**)&Ehi,   g_Ehi);
    cudaGetSymbolAddress((void**)&Elo,   g_Elo);
    cudaGetSymbolAddress((void**)&qkThi, g_qkThi);
    cudaGetSymbolAddress((void**)&qkTlo, g_qkTlo);
    cudaGetSymbolAddress((void**)&ovThi, g_ovThi);
    cudaGetSymbolAddress((void**)&ovTlo, g_ovTlo);
    cudaGetSymbolAddress((void**)&Qhi,   g_Qhi);
    cudaGetSymbolAddress((void**)&Qlo,   g_Qlo);
    cudaGetSymbolAddress((void**)&Vthi,  g_Vthi);
    cudaGetSymbolAddress((void**)&Vtlo,  g_Vtlo);
    cudaGetSymbolAddress((void**)&Phi,   g_Phi);
    cudaGetSymbolAddress((void**)&Plo,   g_Plo);

    cudaFuncSetAttribute(gemm_f16<false, false, false, true>,
                         cudaFuncAttributeMaxDynamicSharedMemorySize, SMEM_BYTES);
    cudaFuncSetAttribute(gemm_f16<true, false, true, false>,
                         cudaFuncAttributeMaxDynamicSharedMemorySize, SMEM_BYTES);
    cudaFuncSetAttribute(gemm_f16<false, true, false, false>,
                         cudaFuncAttributeMaxDynamicSharedMemorySize, SMEM_BYTES);

    // operand preparation
    convert_hilo<<<(N_CTX * D_MODEL / 4 + 255) / 256, 256>>>(E, Ehi, Elo, N_CTX * D_MODEL / 4);
    dim3 tb(32, 8), tg(64, 64);
    transpose_hilo2048<<<tg, tb>>>(qk, qkThi, qkTlo);
    transpose_hilo2048<<<tg, tb>>>(ov, ovThi, ovTlo);

    // Q = E @ qk  (f16 hi/lo out)
    gemm_f16<false, false, false, true><<<dim3(16, 32), 512, SMEM_BYTES>>>(
        Ehi, Elo, qkThi, qkTlo, nullptr, Qhi, Qlo, D_MODEL, D_MODEL, D_MODEL, D_MODEL);
    // Vt = (E @ ov)^T  (f16 hi/lo out)   Vt[d][t] = sum_j ovT[d][j] * E[t][j]
    gemm_f16<false, false, false, true><<<dim3(32, 16), 512, SMEM_BYTES>>>(
        ovThi, ovTlo, Ehi, Elo, nullptr, Vthi, Vtlo, D_MODEL, D_MODEL, D_MODEL, N_CTX);
    // S = Q @ E^T  (lower-triangle blocks, -inf mask on diagonal, fp32 out)
    gemm_f16<true, false, true, false><<<dim3(32, 32), 512, SMEM_BYTES>>>(
        Qhi, Qlo, Ehi, Elo, S, nullptr, nullptr, D_MODEL, D_MODEL, D_MODEL, N_CTX);
    // P = softmax rows -> (hi, lo) f16, zero-padded to 128 blocks
    softmax_kernel<<<N_CTX, 256>>>(S, Phi, Plo);
    // out = P @ Vt^T  (fp32 out, K limited to causal extent per row block)
    gemm_f16<false, true, false, false><<<dim3(16, 32), 512, SMEM_BYTES>>>(
        Phi, Plo, Vthi, Vtlo, out, nullptr, nullptr, N_CTX, N_CTX, N_CTX, D_MODEL);
}

// round 15
// speedup vs baseline: 1.0175x; 1.0175x over previous
#include <cuda_runtime.h>
#include <cuda_fp16.h>
#include <math.h>
#include <stdint.h>

#define N_CTX   4096
#define D_MODEL 2048

// ---------------- scratch (allocation-free rule: device globals) ----------
__device__ float  g_S   [(size_t)N_CTX * N_CTX];       // scores (fp32)
__device__ __half g_Ehi [(size_t)N_CTX * D_MODEL];
__device__ __half g_Elo [(size_t)N_CTX * D_MODEL];
__device__ __half g_qkThi[(size_t)D_MODEL * D_MODEL];
__device__ __half g_qkTlo[(size_t)D_MODEL * D_MODEL];
__device__ __half g_ovThi[(size_t)D_MODEL * D_MODEL];
__device__ __half g_ovTlo[(size_t)D_MODEL * D_MODEL];
__device__ __half g_Qhi [(size_t)N_CTX * D_MODEL];
__device__ __half g_Qlo [(size_t)N_CTX * D_MODEL];
__device__ __half g_Vthi[(size_t)D_MODEL * N_CTX];
__device__ __half g_Vtlo[(size_t)D_MODEL * N_CTX];
__device__ __half g_Phi [(size_t)N_CTX * N_CTX];
__device__ __half g_Plo [(size_t)N_CTX * N_CTX];

// ---------------- helpers ---------------------------------------------------
__device__ __forceinline__ uint32_t smem_u32(const void* p) {
    uint32_t a;
    asm("{ .reg .u64 t; cvta.to.shared.u64 t, %1; cvt.u32.u64 %0, t; }"
        : "=r"(a) : "l"(p));
    return a;
}
#define SWZ(o) ((o) ^ (((o) >> 3) & 0x70))

__device__ __forceinline__ uint32_t f2h2(float x, float y) {
    __half2 h = __floats2half2_rn(x, y);
    return reinterpret_cast<uint32_t&>(h);
}
__device__ __forceinline__ void ldsm_x4(uint32_t* r, uint32_t addr) {
    asm volatile("ldmatrix.sync.aligned.m8n8.x4.shared.b16 {%0,%1,%2,%3}, [%4];"
                 : "=r"(r[0]), "=r"(r[1]), "=r"(r[2]), "=r"(r[3]) : "r"(addr));
}
__device__ __forceinline__ void mma16816(float* c, const uint32_t* a, const uint32_t* b) {
    asm volatile(
        "mma.sync.aligned.m16n8k16.row.col.f32.f16.f16.f32 "
        "{%0,%1,%2,%3}, {%4,%5,%6,%7}, {%8,%9}, {%0,%1,%2,%3};"
        : "+f"(c[0]), "+f"(c[1]), "+f"(c[2]), "+f"(c[3])
        : "r"(a[0]), "r"(a[1]), "r"(a[2]), "r"(a[3]), "r"(b[0]), "r"(b[1]));
}
#define CP_ASYNC16(smem, gptr) \
    asm volatile("cp.async.cg.shared.global [%0], [%1], 16;" \
                 :: "r"(smem), "l"(gptr) : "memory")
#define CP_COMMIT()  asm volatile("cp.async.commit_group;" ::: "memory")
#define CP_WAIT1()   asm volatile("cp.async.wait_group 1;" ::: "memory")

// Per-stage SMEM: four 128x64 f16 tiles (SW128 layout, 128B rows), 16 KB each.
static constexpr int OFF_AH = 0;
static constexpr int OFF_AL = 16384;
static constexpr int OFF_BH = 32768;
static constexpr int OFF_BL = 49152;
static constexpr int STAGE_BYTES = 65536;
static constexpr int STAGES = 3;
static constexpr int SMEM_BYTES = STAGES * STAGE_BYTES;   // 192 KB

// ---------------------------------------------------------------------------
// Pipelined split-fp16 HMMA GEMM:  C[M,N] = A[M,K] @ B[N,K]^T
//   256 threads: 2x4 warp grid, 64x32 warp tiles.
//   A,B given as (hi,lo) f16 pairs, K-major. 3 MMA terms: HH + HL + LH.
//   Warps sharing an SMSP start the kk loop at staggered phases so one
//   warp's ldmatrix (crossbar) overlaps the other's MMA (tensor pipe).
// ---------------------------------------------------------------------------
template<bool SKIP_UPPER, bool KLIMIT, bool MASK, bool F16OUT>
__global__ __launch_bounds__(256, 1)
void gemm_f16(const __half* __restrict__ Ahi, const __half* __restrict__ Alo,
              const __half* __restrict__ Bhi, const __half* __restrict__ Blo,
              float* __restrict__ C, __half* __restrict__ Chi, __half* __restrict__ Clo,
              int K, int lda, int ldb, int ldc)
{
    extern __shared__ char sm[];
    const int bx = blockIdx.x, by = blockIdx.y;
    if (SKIP_UPPER && bx > by) return;

    int Kend = K;
    if (KLIMIT) { int lim = (by + 1) * 128; Kend = lim < K ? lim : K; }
    const int nc = Kend >> 6;     // 64-wide K chunks (always >= 2 here)

    const uint32_t sb = smem_u32(sm);
    const int tid  = threadIdx.x;
    const int wid  = tid >> 5;
    const int lane = tid & 31;
    const int warpM = (wid & 1) * 64;
    const int warpN = (wid >> 1) * 32;
    // phase stagger: warps wid and wid+4 share an SMSP -> offsets 0 / 2
    const int koff = ((wid >> 2) & 1) * 2;

    float acc[4][4][4];
#pragma unroll
    for (int mt = 0; mt < 4; mt++)
#pragma unroll
        for (int nt = 0; nt < 4; nt++)
#pragma unroll
            for (int q = 0; q < 4; q++) acc[mt][nt][q] = 0.0f;

    const __half* AhB = Ahi + (size_t)by * 128 * lda;
    const __half* AlB = Alo + (size_t)by * 128 * lda;
    const __half* BhB = Bhi + (size_t)bx * 128 * ldb;
    const __half* BlB = Blo + (size_t)bx * 128 * ldb;

    auto issue = [&](int c) {
        if (c < nc) {
            const int k0 = c << 6;
            const uint32_t st = sb + (c % STAGES) * STAGE_BYTES;
#pragma unroll
            for (int q = 0; q < 4; q++) {
                int i = tid + (q << 8);
                int r = i >> 3, c16 = i & 7;
                uint32_t so = SWZ((uint32_t)(r * 128 + c16 * 16));
                size_t goA = (size_t)r * lda + k0 + c16 * 8;
                size_t goB = (size_t)r * ldb + k0 + c16 * 8;
                CP_ASYNC16(st + OFF_AH + so, AhB + goA);
                CP_ASYNC16(st + OFF_AL + so, AlB + goA);
                CP_ASYNC16(st + OFF_BH + so, BhB + goB);
                CP_ASYNC16(st + OFF_BL + so, BlB + goB);
            }
        }
        CP_COMMIT();
    };

    // ldmatrix lane addressing (constant across chunks)
    const int a_row_l = lane & 15;
    const int a_kh_l  = ((lane >> 4) & 1) * 8;
    const int b_row_l = (lane & 7) + ((lane >> 4) & 1) * 8;
    const int b_kh_l  = ((lane >> 3) & 1) * 8;

    issue(0);
    issue(1);

    for (int c = 0; c < nc; c++) {
        CP_WAIT1();            // chunk c resident (only c+1 may still be in flight)
        __syncthreads();       // all warps done reading stage (c-1)%3; c's data visible

        issue(c + 2);          // refill the stage freed by chunk c-1

        const uint32_t st = sb + (c % STAGES) * STAGE_BYTES;
#pragma unroll
        for (int j = 0; j < 4; j++) {
            const int kk = (j + koff) & 3;   // staggered phase per warp pair
            uint32_t aH[4][4], aL[4][4], bH[2][4], bL[2][4];
#pragma unroll
            for (int mt = 0; mt < 4; mt++) {
                int row = warpM + mt * 16 + a_row_l;
                uint32_t off = SWZ((uint32_t)(row * 128 + (kk * 16 + a_kh_l) * 2));
                ldsm_x4(aH[mt], st + OFF_AH + off);
                ldsm_x4(aL[mt], st + OFF_AL + off);
            }
#pragma unroll
            for (int np = 0; np < 2; np++) {
                int row = warpN + np * 16 + b_row_l;
                uint32_t off = SWZ((uint32_t)(row * 128 + (kk * 16 + b_kh_l) * 2));
                ldsm_x4(bH[np], st + OFF_BH + off);
                ldsm_x4(bL[np], st + OFF_BL + off);
            }
#pragma unroll
            for (int mt = 0; mt < 4; mt++)
#pragma unroll
                for (int nt = 0; nt < 4; nt++)
                    mma16816(acc[mt][nt], aH[mt], &bH[nt >> 1][(nt & 1) * 2]);
#pragma unroll
            for (int mt = 0; mt < 4; mt++)
#pragma unroll
                for (int nt = 0; nt < 4; nt++)
                    mma16816(acc[mt][nt], aH[mt], &bL[nt >> 1][(nt & 1) * 2]);
#pragma unroll
            for (int mt = 0; mt < 4; mt++)
#pragma unroll
                for (int nt = 0; nt < 4; nt++)
                    mma16816(acc[mt][nt], aL[mt], &bH[nt >> 1][(nt & 1) * 2]);
        }
    }

    // ---- epilogue -----------------------------------------------------------
    const int g  = lane >> 2;
    const int t2 = (lane & 3) * 2;
#pragma unroll
    for (int mt = 0; mt < 4; mt++) {
        int grow0 = by * 128 + warpM + mt * 16 + g;
        int grow1 = grow0 + 8;
#pragma unroll
        for (int nt = 0; nt < 4; nt++) {
            int gcol = bx * 128 + warpN + nt * 8 + t2;
            float2 v0 = make_float2(acc[mt][nt][0], acc[mt][nt][1]);
            float2 v1 = make_float2(acc[mt][nt][2], acc[mt][nt][3]);
            if (F16OUT) {
                float hx0 = __half2float(__float2half_rn(v0.x));
                float hy0 = __half2float(__float2half_rn(v0.y));
                float hx1 = __half2float(__float2half_rn(v1.x));
                float hy1 = __half2float(__float2half_rn(v1.y));
                *(uint32_t*)(Chi + (size_t)grow0 * ldc + gcol) = f2h2(v0.x, v0.y);
                *(uint32_t*)(Clo + (size_t)grow0 * ldc + gcol) = f2h2(v0.x - hx0, v0.y - hy0);
                *(uint32_t*)(Chi + (size_t)grow1 * ldc + gcol) = f2h2(v1.x, v1.y);
                *(uint32_t*)(Clo + (size_t)grow1 * ldc + gcol) = f2h2(v1.x - hx1, v1.y - hy1);
            } else {
                if (MASK) {
                    if (gcol     > grow0) v0.x = -INFINITY;
                    if (gcol + 1 > grow0) v0.y = -INFINITY;
                    if (gcol     > grow1) v1.x = -INFINITY;
                    if (gcol + 1 > grow1) v1.y = -INFINITY;
                }
                *(float2*)(C + (size_t)grow0 * ldc + gcol) = v0;
                *(float2*)(C + (size_t)grow1 * ldc + gcol) = v1;
            }
        }
    }
}

// ---------------------------------------------------------------------------
// fp32 -> (hi, lo) f16 elementwise split (for E)
// ---------------------------------------------------------------------------
__global__ void convert_hilo(const float* __restrict__ in,
                             __half* __restrict__ hi, __half* __restrict__ lo, int n4)
{
    int idx = blockIdx.x * blockDim.x + threadIdx.x;
    if (idx >= n4) return;
    float4 v = ((const float4*)in)[idx];
    float hx = __half2float(__float2half_rn(v.x));
    float hy = __half2float(__float2half_rn(v.y));
    float hz = __half2float(__float2half_rn(v.z));
    float hw = __half2float(__float2half_rn(v.w));
    ((uint2*)hi)[idx] = make_uint2(f2h2(v.x, v.y), f2h2(v.z, v.w));
    ((uint2*)lo)[idx] = make_uint2(f2h2(v.x - hx, v.y - hy), f2h2(v.z - hz, v.w - hw));
}

// ---------------------------------------------------------------------------
// 2048x2048 fp32 transpose + split to (hi, lo) f16 (for qk, ov)
// ---------------------------------------------------------------------------
__global__ void transpose_hilo2048(const float* __restrict__ in,
                                   __half* __restrict__ ohi, __half* __restrict__ olo)
{
    __shared__ float t[32][33];
    int x = blockIdx.x * 32 + threadIdx.x;
    int y = blockIdx.y * 32 + threadIdx.y;
#pragma unroll
    for (int j = 0; j < 32; j += 8)
        t[threadIdx.y + j][threadIdx.x] = in[(size_t)(y + j) * D_MODEL + x];
    __syncthreads();
    x = blockIdx.y * 32 + threadIdx.x;
    y = blockIdx.x * 32 + threadIdx.y;
#pragma unroll
    for (int j = 0; j < 32; j += 8) {
        float v  = t[threadIdx.x][threadIdx.y + j];
        __half h = __float2half_rn(v);
        size_t o = (size_t)(y + j) * D_MODEL + x;
        ohi[o] = h;
        olo[o] = __float2half_rn(v - __half2float(h));
    }
}

// ---------------------------------------------------------------------------
// Row softmax (causal): reads fp32 S, writes (hi, lo) f16 P,
// zero-padded up to each row's 128-block limit.
// ---------------------------------------------------------------------------
__global__ void softmax_kernel(const float* __restrict__ S,
                               __half* __restrict__ Phi, __half* __restrict__ Plo)
{
    const int row   = blockIdx.x;
    const int n     = row + 1;
    const int limit = ((row >> 7) + 1) << 7;
    const float* s = S + (size_t)row * N_CTX;

    __shared__ float red[32];
    const int lane = threadIdx.x & 31;
    const int wid  = threadIdx.x >> 5;

    float m = -INFINITY;
    for (int j = threadIdx.x; j < n; j += 256) m = fmaxf(m, s[j]);
#pragma unroll
    for (int o = 16; o; o >>= 1) m = fmaxf(m, __shfl_xor_sync(0xffffffffu, m, o));
    if (lane == 0) red[wid] = m;
    __syncthreads();
    if (threadIdx.x < 32) {
        float v = (threadIdx.x < 8) ? red[threadIdx.x] : -INFINITY;
#pragma unroll
        for (int o = 4; o; o >>= 1) v = fmaxf(v, __shfl_xor_sync(0xffffffffu, v, o));
        if (threadIdx.x == 0) red[0] = v;
    }
    __syncthreads();
    m = red[0];
    __syncthreads();

    float sum = 0.0f;
    for (int j = threadIdx.x; j < n; j += 256) sum += __expf(s[j] - m);
#pragma unroll
    for (int o = 16; o; o >>= 1) sum += __shfl_xor_sync(0xffffffffu, sum, o);
    if (lane == 0) red[wid] = sum;
    __syncthreads();
    if (threadIdx.x < 32) {
        float v = (threadIdx.x < 8) ? red[threadIdx.x] : 0.0f;
#pragma unroll
        for (int o = 4; o; o >>= 1) v += __shfl_xor_sync(0xffffffffu, v, o);
        if (threadIdx.x == 0) red[0] = v;
    }
    __syncthreads();
    const float inv = 1.0f / red[0];

    __half* phi = Phi + (size_t)row * N_CTX;
    __half* plo = Plo + (size_t)row * N_CTX;
    for (int j = threadIdx.x; j < limit; j += 256) {
        float p = (j < n) ? __expf(s[j] - m) * inv : 0.0f;
        __half h = __float2half_rn(p);
        phi[j] = h;
        plo[j] = __float2half_rn(p - __half2float(h));
    }
}

// ---------------------------------------------------------------------------
extern "C" void kernel_launch(void* const* d_in, const int* in_sizes, int n_in,
                              void* d_out, int out_size)
{
    const float* E  = (const float*)d_in[0];   // [4096, 2048]
    const float* qk = (const float*)d_in[1];   // [2048, 2048]
    const float* ov = (const float*)d_in[2];   // [2048, 2048]
    float* out = (float*)d_out;                // [4096, 2048]

    float* S;
    __half *Ehi, *Elo, *qkThi, *qkTlo, *ovThi, *ovTlo;
    __half *Qhi, *Qlo, *Vthi, *Vtlo, *Phi, *Plo;
    cudaGetSymbolAddress((void**)&S,     g_S);
    cudaGetSymbolAddress((void**)&Ehi,   g_Ehi);
    cudaGetSymbolAddress((void**)&Elo,   g_Elo);
    cudaGetSymbolAddress((void**)&qkThi, g_qkThi);
    cudaGetSymbolAddress((void**)&qkTlo, g_qkTlo);
    cudaGetSymbolAddress((void**)&ovThi, g_ovThi);
    cudaGetSymbolAddress((void**)&ovTlo, g_ovTlo);
    cudaGetSymbolAddress((void**)&Qhi,   g_Qhi);
    cudaGetSymbolAddress((void**)&Qlo,   g_Qlo);
    cudaGetSymbolAddress((void**)&Vthi,  g_Vthi);
    cudaGetSymbolAddress((void**)&Vtlo,  g_Vtlo);
    cudaGetSymbolAddress((void**)&Phi,   g_Phi);
    cudaGetSymbolAddress((void**)&Plo,   g_Plo);

    cudaFuncSetAttribute(gemm_f16<false, false, false, true>,
                         cudaFuncAttributeMaxDynamicSharedMemorySize, SMEM_BYTES);
    cudaFuncSetAttribute(gemm_f16<true, false, true, false>,
                         cudaFuncAttributeMaxDynamicSharedMemorySize, SMEM_BYTES);
    cudaFuncSetAttribute(gemm_f16<false, true, false, false>,
                         cudaFuncAttributeMaxDynamicSharedMemorySize, SMEM_BYTES);

    // operand preparation
    convert_hilo<<<(N_CTX * D_MODEL / 4 + 255) / 256, 256>>>(E, Ehi, Elo, N_CTX * D_MODEL / 4);
    dim3 tb(32, 8), tg(64, 64);
    transpose_hilo2048<<<tg, tb>>>(qk, qkThi, qkTlo);
    transpose_hilo2048<<<tg, tb>>>(ov, ovThi, ovTlo);

    // Q = E @ qk  (f16 hi/lo out)
    gemm_f16<false, false, false, true><<<dim3(16, 32), 256, SMEM_BYTES>>>(
        Ehi, Elo, qkThi, qkTlo, nullptr, Qhi, Qlo, D_MODEL, D_MODEL, D_MODEL, D_MODEL);
    // Vt = (E @ ov)^T  (f16 hi/lo out)   Vt[d][t] = sum_j ovT[d][j] * E[t][j]
    gemm_f16<false, false, false, true><<<dim3(32, 16), 256, SMEM_BYTES>>>(
        ovThi, ovTlo, Ehi, Elo, nullptr, Vthi, Vtlo, D_MODEL, D_MODEL, D_MODEL, N_CTX);
    // S = Q @ E^T  (lower-triangle blocks, -inf mask on diagonal, fp32 out)
    gemm_f16<true, false, true, false><<<dim3(32, 32), 256, SMEM_BYTES>>>(
        Qhi, Qlo, Ehi, Elo, S, nullptr, nullptr, D_MODEL, D_MODEL, D_MODEL, N_CTX);
    // P = softmax rows -> (hi, lo) f16, zero-padded to 128 blocks
    softmax_kernel<<<N_CTX, 256>>>(S, Phi, Plo);
    // out = P @ Vt^T  (fp32 out, K limited to causal extent per row block)
    gemm_f16<false, true, false, false><<<dim3(16, 32), 256, SMEM_BYTES>>>(
        Phi, Plo, Vthi, Vtlo, out, nullptr, nullptr, N_CTX, N_CTX, N_CTX, D_MODEL);
}

// round 16
// speedup vs baseline: 1.2185x; 1.1975x over previous
#include <cuda_runtime.h>
#include <cuda_fp16.h>
#include <math.h>
#include <stdint.h>

#define N_CTX   4096
#define D_MODEL 2048

// ---------------- scratch (allocation-free rule: device globals) ----------
__device__ float  g_S   [(size_t)N_CTX * N_CTX];       // scores (fp32)
__device__ __half g_Ehi [(size_t)N_CTX * D_MODEL];
__device__ __half g_Elo [(size_t)N_CTX * D_MODEL];
__device__ __half g_qkThi[(size_t)D_MODEL * D_MODEL];
__device__ __half g_qkTlo[(size_t)D_MODEL * D_MODEL];
__device__ __half g_ovThi[(size_t)D_MODEL * D_MODEL];
__device__ __half g_ovTlo[(size_t)D_MODEL * D_MODEL];
__device__ __half g_Qhi [(size_t)N_CTX * D_MODEL];
__device__ __half g_Qlo [(size_t)N_CTX * D_MODEL];
__device__ __half g_Vthi[(size_t)D_MODEL * N_CTX];
__device__ __half g_Vtlo[(size_t)D_MODEL * N_CTX];
__device__ __half g_Phi [(size_t)N_CTX * N_CTX];
__device__ __half g_Plo [(size_t)N_CTX * N_CTX];

// ---------------- helpers ---------------------------------------------------
__device__ __forceinline__ uint32_t smem_u32(const void* p) {
    uint32_t a;
    asm("{ .reg .u64 t; cvta.to.shared.u64 t, %1; cvt.u32.u64 %0, t; }"
        : "=r"(a) : "l"(p));
    return a;
}
#define SWZ(o) ((o) ^ (((o) >> 3) & 0x70))

__device__ __forceinline__ uint32_t f2h2(float x, float y) {
    __half2 h = __floats2half2_rn(x, y);
    return reinterpret_cast<uint32_t&>(h);
}
__device__ __forceinline__ void ldsm_x4(uint32_t* r, uint32_t addr) {
    asm volatile("ldmatrix.sync.aligned.m8n8.x4.shared.b16 {%0,%1,%2,%3}, [%4];"
                 : "=r"(r[0]), "=r"(r[1]), "=r"(r[2]), "=r"(r[3]) : "r"(addr));
}
__device__ __forceinline__ void mma16816(float* c, const uint32_t* a, const uint32_t* b) {
    asm volatile(
        "mma.sync.aligned.m16n8k16.row.col.f32.f16.f16.f32 "
        "{%0,%1,%2,%3}, {%4,%5,%6,%7}, {%8,%9}, {%0,%1,%2,%3};"
        : "+f"(c[0]), "+f"(c[1]), "+f"(c[2]), "+f"(c[3])
        : "r"(a[0]), "r"(a[1]), "r"(a[2]), "r"(a[3]), "r"(b[0]), "r"(b[1]));
}
#define CP_ASYNC16(smem, gptr) \
    asm volatile("cp.async.cg.shared.global [%0], [%1], 16;" \
                 :: "r"(smem), "l"(gptr) : "memory")
#define CP_COMMIT()  asm volatile("cp.async.commit_group;" ::: "memory")
#define CP_WAIT1()   asm volatile("cp.async.wait_group 1;" ::: "memory")

// Per-stage SMEM (CTA tile 128x64, BK=64):
//   A hi/lo: 128 rows x 128B = 16 KB each ; B hi/lo: 64 rows x 128B = 8 KB each
static constexpr int OFF_AH = 0;
static constexpr int OFF_AL = 16384;
static constexpr int OFF_BH = 32768;
static constexpr int OFF_BL = 40960;
static constexpr int STAGE_BYTES = 49152;   // 48 KB
static constexpr int STAGES = 2;
static constexpr int SMEM_BYTES = STAGES * STAGE_BYTES;   // 96 KB -> 2 CTAs/SM

// ---------------------------------------------------------------------------
// Pipelined split-fp16 HMMA GEMM:  C[M,N] = A[M,K] @ B[N,K]^T
//   CTA tile 128x64, 256 threads (8 warps: 4 down M x 2 across N, 32x32 each).
//   2 CTAs/SM: co-resident CTAs have independent barriers, so one CTA's
//   ldmatrix (crossbar) phase overlaps the other's MMA (tensor) phase.
//   3 MMA terms: HH + HL + LH (fp32 accum). Same K-accumulation order as R13.
// ---------------------------------------------------------------------------
template<bool SKIP_UPPER, bool KLIMIT, bool MASK, bool F16OUT>
__global__ __launch_bounds__(256, 2)
void gemm_f16(const __half* __restrict__ Ahi, const __half* __restrict__ Alo,
              const __half* __restrict__ Bhi, const __half* __restrict__ Blo,
              float* __restrict__ C, __half* __restrict__ Chi, __half* __restrict__ Clo,
              int K, int lda, int ldb, int ldc)
{
    extern __shared__ char sm[];
    const int bx = blockIdx.x, by = blockIdx.y;
    // skip blocks entirely above the diagonal (64-wide col blocks, 128-row blocks)
    if (SKIP_UPPER && bx * 64 > by * 128 + 127) return;

    int Kend = K;
    if (KLIMIT) { int lim = (by + 1) * 128; Kend = lim < K ? lim : K; }
    const int nc = Kend >> 6;     // 64-wide K chunks (always >= 2 here)

    const uint32_t sb = smem_u32(sm);
    const int tid  = threadIdx.x;
    const int wid  = tid >> 5;
    const int lane = tid & 31;
    const int warpM = (wid & 3) * 32;    // 4 warps down M
    const int warpN = (wid >> 2) * 32;   // 2 warps across N

    float acc[2][4][4];
#pragma unroll
    for (int mt = 0; mt < 2; mt++)
#pragma unroll
        for (int nt = 0; nt < 4; nt++)
#pragma unroll
            for (int q = 0; q < 4; q++) acc[mt][nt][q] = 0.0f;

    const __half* AhB = Ahi + (size_t)by * 128 * lda;
    const __half* AlB = Alo + (size_t)by * 128 * lda;
    const __half* BhB = Bhi + (size_t)bx * 64 * ldb;
    const __half* BlB = Blo + (size_t)bx * 64 * ldb;

    auto issue = [&](int c) {
        if (c < nc) {
            const int k0 = c << 6;
            const uint32_t st = sb + (c & 1) * STAGE_BYTES;
            // A tiles: 128 rows x 8 granules (hi+lo)
#pragma unroll
            for (int q = 0; q < 4; q++) {
                int i = tid + (q << 8);          // 0..1023
                int r = i >> 3, c16 = i & 7;
                uint32_t so = SWZ((uint32_t)(r * 128 + c16 * 16));
                size_t go = (size_t)r * lda + k0 + c16 * 8;
                CP_ASYNC16(st + OFF_AH + so, AhB + go);
                CP_ASYNC16(st + OFF_AL + so, AlB + go);
            }
            // B tiles: 64 rows x 8 granules (hi+lo)
#pragma unroll
            for (int q = 0; q < 2; q++) {
                int i = tid + (q << 8);          // 0..511
                int r = i >> 3, c16 = i & 7;
                uint32_t so = SWZ((uint32_t)(r * 128 + c16 * 16));
                size_t go = (size_t)r * ldb + k0 + c16 * 8;
                CP_ASYNC16(st + OFF_BH + so, BhB + go);
                CP_ASYNC16(st + OFF_BL + so, BlB + go);
            }
        }
        CP_COMMIT();
    };

    // ldmatrix lane addressing (constant across chunks)
    const int a_row_l = lane & 15;
    const int a_kh_l  = ((lane >> 4) & 1) * 8;
    const int b_row_l = (lane & 7) + ((lane >> 4) & 1) * 8;
    const int b_kh_l  = ((lane >> 3) & 1) * 8;

    issue(0);
    issue(1);

    for (int c = 0; c < nc; c++) {
        CP_WAIT1();            // chunk c resident (only c+1 may still be in flight)
        __syncthreads();

        const uint32_t st = sb + (c & 1) * STAGE_BYTES;
#pragma unroll
        for (int kk = 0; kk < 4; kk++) {
            uint32_t aH[2][4], aL[2][4], bH[2][4], bL[2][4];
#pragma unroll
            for (int mt = 0; mt < 2; mt++) {
                int row = warpM + mt * 16 + a_row_l;
                uint32_t off = SWZ((uint32_t)(row * 128 + (kk * 16 + a_kh_l) * 2));
                ldsm_x4(aH[mt], st + OFF_AH + off);
                ldsm_x4(aL[mt], st + OFF_AL + off);
            }
#pragma unroll
            for (int np = 0; np < 2; np++) {
                int row = warpN + np * 16 + b_row_l;
                uint32_t off = SWZ((uint32_t)(row * 128 + (kk * 16 + b_kh_l) * 2));
                ldsm_x4(bH[np], st + OFF_BH + off);
                ldsm_x4(bL[np], st + OFF_BL + off);
            }
#pragma unroll
            for (int mt = 0; mt < 2; mt++)
#pragma unroll
                for (int nt = 0; nt < 4; nt++)
                    mma16816(acc[mt][nt], aH[mt], &bH[nt >> 1][(nt & 1) * 2]);
#pragma unroll
            for (int mt = 0; mt < 2; mt++)
#pragma unroll
                for (int nt = 0; nt < 4; nt++)
                    mma16816(acc[mt][nt], aH[mt], &bL[nt >> 1][(nt & 1) * 2]);
#pragma unroll
            for (int mt = 0; mt < 2; mt++)
#pragma unroll
                for (int nt = 0; nt < 4; nt++)
                    mma16816(acc[mt][nt], aL[mt], &bH[nt >> 1][(nt & 1) * 2]);
        }
        __syncthreads();       // all warps done reading stage c&1
        issue(c + 2);          // refill it
    }

    // ---- epilogue -----------------------------------------------------------
    const int g  = lane >> 2;
    const int t2 = (lane & 3) * 2;
#pragma unroll
    for (int mt = 0; mt < 2; mt++) {
        int grow0 = by * 128 + warpM + mt * 16 + g;
        int grow1 = grow0 + 8;
#pragma unroll
        for (int nt = 0; nt < 4; nt++) {
            int gcol = bx * 64 + warpN + nt * 8 + t2;
            float2 v0 = make_float2(acc[mt][nt][0], acc[mt][nt][1]);
            float2 v1 = make_float2(acc[mt][nt][2], acc[mt][nt][3]);
            if (F16OUT) {
                float hx0 = __half2float(__float2half_rn(v0.x));
                float hy0 = __half2float(__float2half_rn(v0.y));
                float hx1 = __half2float(__float2half_rn(v1.x));
                float hy1 = __half2float(__float2half_rn(v1.y));
                *(uint32_t*)(Chi + (size_t)grow0 * ldc + gcol) = f2h2(v0.x, v0.y);
                *(uint32_t*)(Clo + (size_t)grow0 * ldc + gcol) = f2h2(v0.x - hx0, v0.y - hy0);
                *(uint32_t*)(Chi + (size_t)grow1 * ldc + gcol) = f2h2(v1.x, v1.y);
                *(uint32_t*)(Clo + (size_t)grow1 * ldc + gcol) = f2h2(v1.x - hx1, v1.y - hy1);
            } else {
                if (MASK) {
                    if (gcol     > grow0) v0.x = -INFINITY;
                    if (gcol + 1 > grow0) v0.y = -INFINITY;
                    if (gcol     > grow1) v1.x = -INFINITY;
                    if (gcol + 1 > grow1) v1.y = -INFINITY;
                }
                *(float2*)(C + (size_t)grow0 * ldc + gcol) = v0;
                *(float2*)(C + (size_t)grow1 * ldc + gcol) = v1;
            }
        }
    }
}

// ---------------------------------------------------------------------------
// fp32 -> (hi, lo) f16 elementwise split (for E)
// ---------------------------------------------------------------------------
__global__ void convert_hilo(const float* __restrict__ in,
                             __half* __restrict__ hi, __half* __restrict__ lo, int n4)
{
    int idx = blockIdx.x * blockDim.x + threadIdx.x;
    if (idx >= n4) return;
    float4 v = ((const float4*)in)[idx];
    float hx = __half2float(__float2half_rn(v.x));
    float hy = __half2float(__float2half_rn(v.y));
    float hz = __half2float(__float2half_rn(v.z));
    float hw = __half2float(__float2half_rn(v.w));
    ((uint2*)hi)[idx] = make_uint2(f2h2(v.x, v.y), f2h2(v.z, v.w));
    ((uint2*)lo)[idx] = make_uint2(f2h2(v.x - hx, v.y - hy), f2h2(v.z - hz, v.w - hw));
}

// ---------------------------------------------------------------------------
// 2048x2048 fp32 transpose + split to (hi, lo) f16 (for qk, ov)
// ---------------------------------------------------------------------------
__global__ void transpose_hilo2048(const float* __restrict__ in,
                                   __half* __restrict__ ohi, __half* __restrict__ olo)
{
    __shared__ float t[32][33];
    int x = blockIdx.x * 32 + threadIdx.x;
    int y = blockIdx.y * 32 + threadIdx.y;
#pragma unroll
    for (int j = 0; j < 32; j += 8)
        t[threadIdx.y + j][threadIdx.x] = in[(size_t)(y + j) * D_MODEL + x];
    __syncthreads();
    x = blockIdx.y * 32 + threadIdx.x;
    y = blockIdx.x * 32 + threadIdx.y;
#pragma unroll
    for (int j = 0; j < 32; j += 8) {
        float v  = t[threadIdx.x][threadIdx.y + j];
        __half h = __float2half_rn(v);
        size_t o = (size_t)(y + j) * D_MODEL + x;
        ohi[o] = h;
        olo[o] = __float2half_rn(v - __half2float(h));
    }
}

// ---------------------------------------------------------------------------
// Row softmax (causal): reads fp32 S, writes (hi, lo) f16 P,
// zero-padded up to each row's 128-block limit.
// ---------------------------------------------------------------------------
__global__ void softmax_kernel(const float* __restrict__ S,
                               __half* __restrict__ Phi, __half* __restrict__ Plo)
{
    const int row   = blockIdx.x;
    const int n     = row + 1;
    const int limit = ((row >> 7) + 1) << 7;
    const float* s = S + (size_t)row * N_CTX;

    __shared__ float red[32];
    const int lane = threadIdx.x & 31;
    const int wid  = threadIdx.x >> 5;

    float m = -INFINITY;
    for (int j = threadIdx.x; j < n; j += 256) m = fmaxf(m, s[j]);
#pragma unroll
    for (int o = 16; o; o >>= 1) m = fmaxf(m, __shfl_xor_sync(0xffffffffu, m, o));
    if (lane == 0) red[wid] = m;
    __syncthreads();
    if (threadIdx.x < 32) {
        float v = (threadIdx.x < 8) ? red[threadIdx.x] : -INFINITY;
#pragma unroll
        for (int o = 4; o; o >>= 1) v = fmaxf(v, __shfl_xor_sync(0xffffffffu, v, o));
        if (threadIdx.x == 0) red[0] = v;
    }
    __syncthreads();
    m = red[0];
    __syncthreads();

    float sum = 0.0f;
    for (int j = threadIdx.x; j < n; j += 256) sum += __expf(s[j] - m);
#pragma unroll
    for (int o = 16; o; o >>= 1) sum += __shfl_xor_sync(0xffffffffu, sum, o);
    if (lane == 0) red[wid] = sum;
    __syncthreads();
    if (threadIdx.x < 32) {
        float v = (threadIdx.x < 8) ? red[threadIdx.x] : 0.0f;
#pragma unroll
        for (int o = 4; o; o >>= 1) v += __shfl_xor_sync(0xffffffffu, v, o);
        if (threadIdx.x == 0) red[0] = v;
    }
    __syncthreads();
    const float inv = 1.0f / red[0];

    __half* phi = Phi + (size_t)row * N_CTX;
    __half* plo = Plo + (size_t)row * N_CTX;
    for (int j = threadIdx.x; j < limit; j += 256) {
        float p = (j < n) ? __expf(s[j] - m) * inv : 0.0f;
        __half h = __float2half_rn(p);
        phi[j] = h;
        plo[j] = __float2half_rn(p - __half2float(h));
    }
}

// ---------------------------------------------------------------------------
extern "C" void kernel_launch(void* const* d_in, const int* in_sizes, int n_in,
                              void* d_out, int out_size)
{
    const float* E  = (const float*)d_in[0];   // [4096, 2048]
    const float* qk = (const float*)d_in[1];   // [2048, 2048]
    const float* ov = (const float*)d_in[2];   // [2048, 2048]
    float* out = (float*)d_out;                // [4096, 2048]

    float* S;
    __half *Ehi, *Elo, *qkThi, *qkTlo, *ovThi, *ovTlo;
    __half *Qhi, *Qlo, *Vthi, *Vtlo, *Phi, *Plo;
    cudaGetSymbolAddress((void**)&S,     g_S);
    cudaGetSymbolAddress((void**)&Ehi,   g_Ehi);
    cudaGetSymbolAddress((void**)&Elo,   g_Elo);
    cudaGetSymbolAddress((void**)&qkThi, g_qkThi);
    cudaGetSymbolAddress((void**)&qkTlo, g_qkTlo);
    cudaGetSymbolAddress((void**)&ovThi, g_ovThi);
    cudaGetSymbolAddress((void**)&ovTlo, g_ovTlo);
    cudaGetSymbolAddress((void**)&Qhi,   g_Qhi);
    cudaGetSymbolAddress((void**)&Qlo,   g_Qlo);
    cudaGetSymbolAddress((void**)&Vthi,  g_Vthi);
    cudaGetSymbolAddress((void**)&Vtlo,  g_Vtlo);
    cudaGetSymbolAddress((void**)&Phi,   g_Phi);
    cudaGetSymbolAddress((void**)&Plo,   g_Plo);

    cudaFuncSetAttribute(gemm_f16<false, false, false, true>,
                         cudaFuncAttributeMaxDynamicSharedMemorySize, SMEM_BYTES);
    cudaFuncSetAttribute(gemm_f16<true, false, true, false>,
                         cudaFuncAttributeMaxDynamicSharedMemorySize, SMEM_BYTES);
    cudaFuncSetAttribute(gemm_f16<false, true, false, false>,
                         cudaFuncAttributeMaxDynamicSharedMemorySize, SMEM_BYTES);

    // operand preparation
    convert_hilo<<<(N_CTX * D_MODEL / 4 + 255) / 256, 256>>>(E, Ehi, Elo, N_CTX * D_MODEL / 4);
    dim3 tb(32, 8), tg(64, 64);
    transpose_hilo2048<<<tg, tb>>>(qk, qkThi, qkTlo);
    transpose_hilo2048<<<tg, tb>>>(ov, ovThi, ovTlo);

    // Q = E @ qk  (f16 hi/lo out)
    gemm_f16<false, false, false, true><<<dim3(32, 32), 256, SMEM_BYTES>>>(
        Ehi, Elo, qkThi, qkTlo, nullptr, Qhi, Qlo, D_MODEL, D_MODEL, D_MODEL, D_MODEL);
    // Vt = (E @ ov)^T  (f16 hi/lo out)   Vt[d][t] = sum_j ovT[d][j] * E[t][j]
    gemm_f16<false, false, false, true><<<dim3(64, 16), 256, SMEM_BYTES>>>(
        ovThi, ovTlo, Ehi, Elo, nullptr, Vthi, Vtlo, D_MODEL, D_MODEL, D_MODEL, N_CTX);
    // S = Q @ E^T  (blocks not strictly above diagonal; -inf mask elementwise)
    gemm_f16<true, false, true, false><<<dim3(64, 32), 256, SMEM_BYTES>>>(
        Qhi, Qlo, Ehi, Elo, S, nullptr, nullptr, D_MODEL, D_MODEL, D_MODEL, N_CTX);
    // P = softmax rows -> (hi, lo) f16, zero-padded to 128 blocks
    softmax_kernel<<<N_CTX, 256>>>(S, Phi, Plo);
    // out = P @ Vt^T  (fp32 out, K limited to causal extent per row block)
    gemm_f16<false, true, false, false><<<dim3(32, 32), 256, SMEM_BYTES>>>(
        Phi, Plo, Vthi, Vtlo, out, nullptr, nullptr, N_CTX, N_CTX, N_CTX, D_MODEL);
}